// round 1
// baseline (speedup 1.0000x reference)
#include <cuda_runtime.h>
#include <math.h>

#define N_TOK   49
#define DIM     128
#define NHEADS  4
#define HD      32
#define NWIN    64
#define THREADS 384

// dynamic smem layout (floats):
// [0,6272)       : phase1 = x tile (49x128) ; phase2 = mask(2401) | relidx(int,2401)@2432 | rel_table(676)@4864
// [6272,12544)   : q_s   [h][n][d]  (q pre-scaled)
// [12544,18816)  : kT_s  [h][d][n]
// [18816,25088)  : v_s   [h][n][d]
#define SMEM_FLOATS 25088

__global__ __launch_bounds__(THREADS)
void win_attn_kernel(const float* __restrict__ x,
                     const float* __restrict__ mask,
                     const float* __restrict__ W,      // (384,128) row-major
                     const float* __restrict__ bvec,   // (384,)
                     const float* __restrict__ rel_table, // (169,4)
                     float* __restrict__ out)
{
    extern __shared__ float sm[];
    float* xs   = sm;            // 6272
    float* q_s  = sm + 6272;     // 6272
    float* kT_s = sm + 12544;    // 6272
    float* v_s  = sm + 18816;    // 6272
    // phase-2 aliases of the x region
    float* mask_s  = sm;                     // 2401 floats
    int*   ridx_s  = (int*)(sm + 2432);      // 2401 ints
    float* rel_s   = sm + 4864;              // 676 floats

    const int b = blockIdx.x;
    const int t = threadIdx.x;

    // ---- phase 0: stage x window into smem (coalesced float4) ----
    {
        const float4* xg  = (const float4*)(x + (size_t)b * (N_TOK * DIM));
        float4*       xs4 = (float4*)xs;
        #pragma unroll
        for (int i = t; i < (N_TOK * DIM) / 4; i += THREADS) xs4[i] = xg[i];
    }
    __syncthreads();

    // ---- phase 1: QKV projection. thread t owns output column o=t ----
    // column o -> (head h, dim d, which) with o = h*96 + d*3 + which  (torch split order)
    {
        const int o     = t;
        const int h     = o / 96;
        const int rem   = o - h * 96;
        const int d     = rem / 3;
        const int which = rem - d * 3;

        float acc[N_TOK];
        const float bo = bvec[o];
        #pragma unroll
        for (int n = 0; n < N_TOK; n++) acc[n] = bo;

        const float4* wrow = (const float4*)(W + o * DIM);
        const float4* xs4  = (const float4*)xs;
        for (int kk = 0; kk < DIM / 4; kk++) {
            const float4 w4 = __ldg(&wrow[kk]);
            #pragma unroll
            for (int n = 0; n < N_TOK; n++) {
                const float4 x4 = xs4[n * (DIM / 4) + kk];   // LDS.128 broadcast across warp
                acc[n] = fmaf(x4.x, w4.x, acc[n]);
                acc[n] = fmaf(x4.y, w4.y, acc[n]);
                acc[n] = fmaf(x4.z, w4.z, acc[n]);
                acc[n] = fmaf(x4.w, w4.w, acc[n]);
            }
        }

        const float scale = 0.17677669529663687f;  // 1/sqrt(32), folded into q
        if (which == 0) {
            #pragma unroll
            for (int n = 0; n < N_TOK; n++) q_s[(h * N_TOK + n) * HD + d] = acc[n] * scale;
        } else if (which == 1) {
            #pragma unroll
            for (int n = 0; n < N_TOK; n++) kT_s[(h * HD + d) * N_TOK + n] = acc[n];
        } else {
            #pragma unroll
            for (int n = 0; n < N_TOK; n++) v_s[(h * N_TOK + n) * HD + d] = acc[n];
        }
    }
    __syncthreads();

    // ---- phase 2: stage mask window, rel indices, rel_table (alias x region) ----
    {
        const int w = b & (NWIN - 1);
        const float* mw = mask + (size_t)w * (N_TOK * N_TOK);
        for (int i = t; i < N_TOK * N_TOK; i += THREADS) mask_s[i] = mw[i];
        for (int i = t; i < N_TOK * N_TOK; i += THREADS) {
            const int n = i / N_TOK, m = i - n * N_TOK;
            const int dh = n / 7 - m / 7 + 6;
            const int dw = n % 7 - m % 7 + 6;
            ridx_s[i] = dh * 13 + dw;
        }
        for (int i = t; i < 169 * NHEADS; i += THREADS) rel_s[i] = rel_table[i];
    }
    __syncthreads();

    // ---- phase 3: attention, one warp per (head,row) ----
    const int lane = t & 31;
    const int wid  = t >> 5;
    const bool valid1 = (lane + 32) < N_TOK;   // lanes 0..16 own a second key
    float* outb = out + (size_t)b * (N_TOK * DIM);

    for (int r = wid; r < NHEADS * N_TOK; r += THREADS / 32) {
        const int h = r / N_TOK;
        const int n = r - h * N_TOK;
        const int m0 = lane;
        const int m1 = valid1 ? (lane + 32) : 0;  // clamped; result discarded if !valid1

        const float* qrow = q_s + (h * N_TOK + n) * HD;
        const float* kTb  = kT_s + h * HD * N_TOK;

        float s0 = 0.f, s1 = 0.f;
        #pragma unroll
        for (int dd = 0; dd < HD; dd++) {
            const float qd = qrow[dd];                 // smem broadcast
            s0 = fmaf(qd, kTb[dd * N_TOK + m0], s0);   // consecutive lanes -> conflict-free
            s1 = fmaf(qd, kTb[dd * N_TOK + m1], s1);
        }
        s0 += rel_s[ridx_s[n * N_TOK + m0] * NHEADS + h] + mask_s[n * N_TOK + m0];
        if (valid1)
            s1 += rel_s[ridx_s[n * N_TOK + (lane + 32)] * NHEADS + h] + mask_s[n * N_TOK + lane + 32];
        else
            s1 = -1e30f;

        // warp softmax over 49 scores
        float mx = fmaxf(s0, s1);
        #pragma unroll
        for (int off = 16; off; off >>= 1) mx = fmaxf(mx, __shfl_xor_sync(0xffffffffu, mx, off));
        float p0 = __expf(s0 - mx);
        float p1 = valid1 ? __expf(s1 - mx) : 0.f;
        float sum = p0 + p1;
        #pragma unroll
        for (int off = 16; off; off >>= 1) sum += __shfl_xor_sync(0xffffffffu, sum, off);
        const float inv = 1.0f / sum;
        p0 *= inv; p1 *= inv;

        // out[n][h*32 + lane] = sum_m p[m] * v[m][lane]
        float acc = 0.f;
        const float* vb = v_s + h * N_TOK * HD + lane;
        #pragma unroll
        for (int m = 0; m < N_TOK; m++) {
            const float pm = __shfl_sync(0xffffffffu, (m < 32) ? p0 : p1, m & 31);
            acc = fmaf(pm, vb[m * HD], acc);
        }
        outb[n * DIM + h * HD + lane] = acc;   // coalesced
    }
}

extern "C" void kernel_launch(void* const* d_in, const int* in_sizes, int n_in,
                              void* d_out, int out_size)
{
    const float* x    = (const float*)d_in[0];
    const float* mask = (const float*)d_in[1];
    const float* W    = (const float*)d_in[2];
    const float* bvec = (const float*)d_in[3];
    const float* rel  = (const float*)d_in[4];
    float* out = (float*)d_out;

    const int smem_bytes = SMEM_FLOATS * (int)sizeof(float);  // 100352
    cudaFuncSetAttribute(win_attn_kernel,
                         cudaFuncAttributeMaxDynamicSharedMemorySize, smem_bytes);
    win_attn_kernel<<<4096, THREADS, smem_bytes>>>(x, mask, W, bvec, rel, out);
}